// round 1
// baseline (speedup 1.0000x reference)
#include <cuda_runtime.h>

// y = FWHT(G * Perm(FWHT(x * B))) , orthonormal, L = 16384, fused one-pass.
//
// One CTA (1024 threads) per row. Each thread holds 16 values in registers.
// A radix-16 register FWHT covers 4 of the 14 index bits per phase; bit
// groups are rotated into registers via shared-memory transposes:
//   FWHT1: bits[0..3] (from coalesced float4 global load) -> T -> bits[4..7]
//          -> T -> bits[8..11] -> T -> bits[12..13]
//   perm : write, sync, gather r[i] = G[n] * Y1[Pi[n]]  (layout n = (i<<10)+t)
//   FWHT2: bits[10..13] -> T -> bits[6..9] -> T -> bits[2..5] -> T -> bits[0..1]
//          -> scaled float4 store (total scale 1/16384 = orthonormal^2)
// SMEM padded addr(n) = n + 4*(n>>6): all strided transpose patterns are
// bank-conflict-free; contiguous float4 pattern has a benign 2-way group conflict.

#define L_N       16384
#define NT        1024
#define SMEM_WORDS (L_N + 4 * (L_N / 64))   // 16384 + 1024 = 17408
#define SMEM_BYTES (SMEM_WORDS * 4)         // 69632

__device__ __forceinline__ int sw(int n) { return n + ((n >> 6) << 2); }

__device__ __forceinline__ void bfly(float &a, float &b) {
    float t0 = a + b;
    float t1 = a - b;
    a = t0; b = t1;
}

__device__ __forceinline__ void fwht16(float r[16]) {
#pragma unroll
    for (int m = 1; m < 16; m <<= 1) {
#pragma unroll
        for (int i = 0; i < 16; i++) {
            if ((i & m) == 0) bfly(r[i], r[i | m]);
        }
    }
}

__global__ __launch_bounds__(NT, 1)
void fwht_fused_kernel(const float* __restrict__ x,
                       const float* __restrict__ Bv,
                       const float* __restrict__ Gv,
                       const int*   __restrict__ Pi,
                       float* __restrict__ out) {
    extern __shared__ float s[];
    const int t = threadIdx.x;
    const size_t row = blockIdx.x;

    const float4* __restrict__ x4 = reinterpret_cast<const float4*>(x + row * L_N);
    const float4* __restrict__ B4 = reinterpret_cast<const float4*>(Bv);

    float r[16];

    // ================= FWHT #1 =================
    // Q0: contiguous load, n = 16t + i ; registers cover bits 0..3
#pragma unroll
    for (int k = 0; k < 4; k++) {
        float4 xv = x4[(t << 2) + k];
        float4 bv = B4[(t << 2) + k];
        r[4 * k + 0] = xv.x * bv.x;
        r[4 * k + 1] = xv.y * bv.y;
        r[4 * k + 2] = xv.z * bv.z;
        r[4 * k + 3] = xv.w * bv.w;
    }
    fwht16(r);  // bits 0..3

    // store contiguous (float4, swizzled)
#pragma unroll
    for (int k = 0; k < 4; k++) {
        int n = (t << 4) + (k << 2);
        *reinterpret_cast<float4*>(&s[sw(n)]) =
            make_float4(r[4 * k], r[4 * k + 1], r[4 * k + 2], r[4 * k + 3]);
    }
    __syncthreads();

    // Q1: n = ((t>>4)<<8) | (i<<4) | (t&15) ; registers cover bits 4..7
    {
        int hi = (t >> 4) << 8, lo = t & 15;
#pragma unroll
        for (int i = 0; i < 16; i++) r[i] = s[sw(hi | (i << 4) | lo)];
        fwht16(r);  // bits 4..7
#pragma unroll
        for (int i = 0; i < 16; i++) s[sw(hi | (i << 4) | lo)] = r[i];
    }
    __syncthreads();

    // Q2: n = ((t>>8)<<12) | (i<<8) | (t&255) ; registers cover bits 8..11
    {
        int hi = (t >> 8) << 12, lo = t & 255;
#pragma unroll
        for (int i = 0; i < 16; i++) r[i] = s[sw(hi | (i << 8) | lo)];
        fwht16(r);  // bits 8..11
#pragma unroll
        for (int i = 0; i < 16; i++) s[sw(hi | (i << 8) | lo)] = r[i];
    }
    __syncthreads();

    // P0: n = (i<<10) + t ; registers cover bits 10..13, apply only bits 12,13
    {
#pragma unroll
        for (int i = 0; i < 16; i++) r[i] = s[sw((i << 10) + t)];
#pragma unroll
        for (int i = 0; i < 16; i++) if ((i & 4) == 0) bfly(r[i], r[i | 4]);
#pragma unroll
        for (int i = 0; i < 16; i++) if ((i & 8) == 0) bfly(r[i], r[i | 8]);
#pragma unroll
        for (int i = 0; i < 16; i++) s[sw((i << 10) + t)] = r[i];
    }
    __syncthreads();

    // ================= permutation + G =================
    // r[i] = G[n] * Y1[Pi[n]] , n = (i<<10) + t  (regs end up in P0 layout)
#pragma unroll
    for (int i = 0; i < 16; i++) {
        int n = (i << 10) + t;
        int p = __ldg(&Pi[n]);
        r[i] = __ldg(&Gv[n]) * s[sw(p)];
    }
    __syncthreads();  // all gathers done before smem is overwritten

    // ================= FWHT #2 =================
    fwht16(r);  // bits 10..13
#pragma unroll
    for (int i = 0; i < 16; i++) s[sw((i << 10) + t)] = r[i];
    __syncthreads();

    // P1: n = ((t>>6)<<10) | (i<<6) | (t&63) ; bits 6..9
    {
        int hi = (t >> 6) << 10, lo = t & 63;
#pragma unroll
        for (int i = 0; i < 16; i++) r[i] = s[sw(hi | (i << 6) | lo)];
        fwht16(r);  // bits 6..9
#pragma unroll
        for (int i = 0; i < 16; i++) s[sw(hi | (i << 6) | lo)] = r[i];
    }
    __syncthreads();

    // P2: n = ((t>>2)<<6) | (i<<2) | (t&3) ; bits 2..5
    {
        int hi = (t >> 2) << 6, lo = t & 3;
#pragma unroll
        for (int i = 0; i < 16; i++) r[i] = s[sw(hi | (i << 2) | lo)];
        fwht16(r);  // bits 2..5
#pragma unroll
        for (int i = 0; i < 16; i++) s[sw(hi | (i << 2) | lo)] = r[i];
    }
    __syncthreads();

    // P3: contiguous read, bits 0..1, scale by 1/16384, vectorized store
    {
        const float sc = 1.0f / 16384.0f;
        float4* __restrict__ o4 = reinterpret_cast<float4*>(out + row * L_N + (t << 4));
#pragma unroll
        for (int k = 0; k < 4; k++) {
            int n = (t << 4) + (k << 2);
            float4 v = *reinterpret_cast<const float4*>(&s[sw(n)]);
            float a0 = v.x, a1 = v.y, a2 = v.z, a3 = v.w;
            bfly(a0, a1); bfly(a2, a3);  // h = 1
            bfly(a0, a2); bfly(a1, a3);  // h = 2
            o4[k] = make_float4(a0 * sc, a1 * sc, a2 * sc, a3 * sc);
        }
    }
}

extern "C" void kernel_launch(void* const* d_in, const int* in_sizes, int n_in,
                              void* d_out, int out_size) {
    const float* x  = (const float*)d_in[0];
    const float* B  = (const float*)d_in[1];
    const float* G  = (const float*)d_in[2];
    const int*   Pi = (const int*)d_in[3];
    float* out = (float*)d_out;

    int rows = in_sizes[0] / L_N;

    // Idempotent, host-side, not a stream op: safe under graph capture.
    cudaFuncSetAttribute(fwht_fused_kernel,
                         cudaFuncAttributeMaxDynamicSharedMemorySize, SMEM_BYTES);

    fwht_fused_kernel<<<rows, NT, SMEM_BYTES>>>(x, B, G, Pi, out);
}

// round 2
// speedup vs baseline: 1.0200x; 1.0200x over previous
#include <cuda_runtime.h>

// y = FWHT(G * Perm(FWHT(x * B))), orthonormal, L = 16384, fused one-pass.
//
// Radix-32: one CTA (512 threads) per row, 32 values/thread (5 index bits in
// registers). Each FWHT-16384 (14 bits) = 3 register phases (5+5+4 bits) with
// 2 smem transposes. Layouts:
//   A: n = 32t + j            (regs = bits 0..4,  contiguous -> float4 smem ops)
//   B: n = (t>>5)<<10 | j<<5 | (t&31)   (regs = bits 5..9, stride-32 scalar)
//   C: n = (jh<<10) | (t<<1) | jl       (regs = bits 10..13 x bit0, float2 smem ops)
// Pipeline: LDG(A) F(0-4) | T->B F(5-9) | T->C F(10-13) | store nat, gather+G |
//           F(10-13) | T->B F(5-9) | T->A F(0-4), scale, STG.
// Padding addr(n) = n + 4*(n>>5): conflict-free for A (LDS.128), B (scalar),
// C (LDS.64); preserves 16B alignment. Only the random gather keeps conflicts.
// __launch_bounds__(512,2): 2 CTAs/SM (144KB smem) to overlap barrier tails.

#define L_N        16384
#define NT         512
#define SMEM_WORDS (L_N + 4 * (L_N / 32))   // 16384 + 2048 = 18432
#define SMEM_BYTES (SMEM_WORDS * 4)         // 73728

__device__ __forceinline__ int sw(int n) { return n + ((n >> 5) << 2); }

__device__ __forceinline__ void bfly(float &a, float &b) {
    float t0 = a + b;
    float t1 = a - b;
    a = t0; b = t1;
}

// 5-bit FWHT over r[0..31] (butterflies on all reg-index bits)
__device__ __forceinline__ void fwht32(float r[32]) {
#pragma unroll
    for (int m = 1; m < 32; m <<= 1) {
#pragma unroll
        for (int i = 0; i < 32; i++) {
            if ((i & m) == 0) bfly(r[i], r[i | m]);
        }
    }
}

// 4-bit FWHT over jh (r indexed as r[2*jh + jl], both jl lanes)
__device__ __forceinline__ void fwht16x2(float r[32]) {
#pragma unroll
    for (int m = 1; m < 16; m <<= 1) {
#pragma unroll
        for (int ih = 0; ih < 16; ih++) {
            if ((ih & m) == 0) {
                bfly(r[2 * ih],     r[2 * (ih | m)]);
                bfly(r[2 * ih + 1], r[2 * (ih | m) + 1]);
            }
        }
    }
}

__global__ __launch_bounds__(NT, 2)
void fwht_fused_kernel(const float* __restrict__ x,
                       const float* __restrict__ Bv,
                       const float* __restrict__ Gv,
                       const int*   __restrict__ Pi,
                       float* __restrict__ out) {
    extern __shared__ float s[];
    const int t = threadIdx.x;
    const size_t row = blockIdx.x;

    float r[32];

    // ===== FWHT #1, phase A: bits 0..4 =====
    {
        const float4* __restrict__ x4 = reinterpret_cast<const float4*>(x + row * L_N);
        const float4* __restrict__ B4 = reinterpret_cast<const float4*>(Bv);
#pragma unroll
        for (int k = 0; k < 8; k++) {
            float4 xv = x4[(t << 3) + k];
            float4 bv = B4[(t << 3) + k];
            r[4 * k + 0] = xv.x * bv.x;
            r[4 * k + 1] = xv.y * bv.y;
            r[4 * k + 2] = xv.z * bv.z;
            r[4 * k + 3] = xv.w * bv.w;
        }
    }
    fwht32(r);

    // store layout A (float4, conflict-free under sw)
#pragma unroll
    for (int k = 0; k < 8; k++) {
        int n = (t << 5) + (k << 2);
        *reinterpret_cast<float4*>(&s[sw(n)]) =
            make_float4(r[4 * k], r[4 * k + 1], r[4 * k + 2], r[4 * k + 3]);
    }
    __syncthreads();

    // ===== FWHT #1, phase B: bits 5..9 =====
    {
        const int hi = (t >> 5) << 10, lo = t & 31;
#pragma unroll
        for (int j = 0; j < 32; j++) r[j] = s[sw(hi | (j << 5) | lo)];
        fwht32(r);
#pragma unroll
        for (int j = 0; j < 32; j++) s[sw(hi | (j << 5) | lo)] = r[j];
    }
    __syncthreads();

    // ===== FWHT #1, phase C: bits 10..13 =====
    const int c0 = t << 1;
#pragma unroll
    for (int ih = 0; ih < 16; ih++) {
        float2 v = *reinterpret_cast<const float2*>(&s[sw((ih << 10) | c0)]);
        r[2 * ih] = v.x; r[2 * ih + 1] = v.y;
    }
    fwht16x2(r);
    // store at true indices (natural) so the gather can address s by n
#pragma unroll
    for (int ih = 0; ih < 16; ih++) {
        *reinterpret_cast<float2*>(&s[sw((ih << 10) | c0)]) =
            make_float2(r[2 * ih], r[2 * ih + 1]);
    }
    __syncthreads();

    // ===== permutation + G (into layout C) =====
#pragma unroll
    for (int ih = 0; ih < 16; ih++) {
        int n = (ih << 10) | c0;
        int2   p  = *reinterpret_cast<const int2*>(&Pi[n]);
        float2 gv = *reinterpret_cast<const float2*>(&Gv[n]);
        r[2 * ih]     = gv.x * s[sw(p.x)];
        r[2 * ih + 1] = gv.y * s[sw(p.y)];
    }
    __syncthreads();   // all gathers complete before smem is overwritten

    // ===== FWHT #2, phase C: bits 10..13 =====
    fwht16x2(r);
#pragma unroll
    for (int ih = 0; ih < 16; ih++) {
        *reinterpret_cast<float2*>(&s[sw((ih << 10) | c0)]) =
            make_float2(r[2 * ih], r[2 * ih + 1]);
    }
    __syncthreads();

    // ===== FWHT #2, phase B: bits 5..9 =====
    {
        const int hi = (t >> 5) << 10, lo = t & 31;
#pragma unroll
        for (int j = 0; j < 32; j++) r[j] = s[sw(hi | (j << 5) | lo)];
        fwht32(r);
#pragma unroll
        for (int j = 0; j < 32; j++) s[sw(hi | (j << 5) | lo)] = r[j];
    }
    __syncthreads();

    // ===== FWHT #2, phase A: bits 0..4, scale, store =====
    {
        const float sc = 1.0f / 16384.0f;
#pragma unroll
        for (int k = 0; k < 8; k++) {
            int n = (t << 5) + (k << 2);
            float4 v = *reinterpret_cast<const float4*>(&s[sw(n)]);
            r[4 * k + 0] = v.x; r[4 * k + 1] = v.y;
            r[4 * k + 2] = v.z; r[4 * k + 3] = v.w;
        }
        fwht32(r);
        float4* __restrict__ o4 = reinterpret_cast<float4*>(out + row * L_N);
#pragma unroll
        for (int k = 0; k < 8; k++) {
            o4[(t << 3) + k] = make_float4(r[4 * k] * sc, r[4 * k + 1] * sc,
                                           r[4 * k + 2] * sc, r[4 * k + 3] * sc);
        }
    }
}

extern "C" void kernel_launch(void* const* d_in, const int* in_sizes, int n_in,
                              void* d_out, int out_size) {
    const float* x  = (const float*)d_in[0];
    const float* B  = (const float*)d_in[1];
    const float* G  = (const float*)d_in[2];
    const int*   Pi = (const int*)d_in[3];
    float* out = (float*)d_out;

    int rows = in_sizes[0] / L_N;

    cudaFuncSetAttribute(fwht_fused_kernel,
                         cudaFuncAttributeMaxDynamicSharedMemorySize, SMEM_BYTES);

    fwht_fused_kernel<<<rows, NT, SMEM_BYTES>>>(x, B, G, Pi, out);
}

// round 3
// speedup vs baseline: 1.2904x; 1.2651x over previous
#include <cuda_runtime.h>

// y = FWHT(G * Perm(FWHT(x * B))), orthonormal, L = 16384, fused one-pass.
//
// Radix-32, 512 threads/CTA, one row/CTA, 2 CTAs/SM. FWHT-16384 (14 bits) done
// in 3 register phases; FWHT stages commute, so phases may own ANY bit subset:
//   P1: regs = n bits {0,1,11,12,13}, lanes = bits 2..6  -> global IO coalesced
//   P2: regs = n bits {2,3,8,9,10},   lanes = bits {0,1,4,5,6} (scalar smem)
//   P3: regs = n bits {4,5,6,7}+bit0, lanes = bits {1,2,3,12,8} (float2 smem)
// SMEM XOR swizzle w(n) = n ^ ((((n>>5)^(n>>10))&7)<<2): bijective, preserves
// float4/float2 groups, zero padding (64KB). Bank bits: b0=n0, b1=n1,
// b2=n2^n5^n10, b3=n3^n6^n11, b4=n4^n7^n12 -> all three phase layouts are
// bank-conflict-free (P1 per STS.128 quarter, P3 per LDS.64 half-warp).
// Only the random permutation gather has inherent conflicts.

#define L_N        16384
#define NT         512
#define SMEM_BYTES (L_N * 4)   // 65536, no padding needed with XOR swizzle

__device__ __forceinline__ int sw(int n) {
    return n ^ (((((unsigned)n >> 5) ^ ((unsigned)n >> 10)) & 7u) << 2);
}

__device__ __forceinline__ void bfly(float &a, float &b) {
    float t0 = a + b;
    float t1 = a - b;
    a = t0; b = t1;
}

// full 5-bit FWHT over reg index
__device__ __forceinline__ void fwht32(float r[32]) {
#pragma unroll
    for (int m = 1; m < 32; m <<= 1) {
#pragma unroll
        for (int i = 0; i < 32; i++) {
            if ((i & m) == 0) bfly(r[i], r[i | m]);
        }
    }
}

// 4-bit FWHT over high reg index (r[2*ih + jl], jl is a passenger bit)
__device__ __forceinline__ void fwht16x2(float r[32]) {
#pragma unroll
    for (int m = 1; m < 16; m <<= 1) {
#pragma unroll
        for (int ih = 0; ih < 16; ih++) {
            if ((ih & m) == 0) {
                bfly(r[2 * ih],     r[2 * (ih | m)]);
                bfly(r[2 * ih + 1], r[2 * (ih | m) + 1]);
            }
        }
    }
}

__global__ __launch_bounds__(NT, 2)
void fwht_fused_kernel(const float* __restrict__ x,
                       const float* __restrict__ Bv,
                       const float* __restrict__ Gv,
                       const int*   __restrict__ Pi,
                       float* __restrict__ out) {
    extern __shared__ float s[];
    const int t = threadIdx.x;
    const size_t row = blockIdx.x;

    float r[32];

    // thread->n base for P2: lanes l0..l4 -> n0,n1,n4,n5,n6 ; t5->n7, t6..t8->n11..13
    const int p2base = (t & 3)
                     | (((t >> 2) & 7) << 4)
                     | (((t >> 5) & 1) << 7)
                     | ((t >> 6) << 11);
    // thread->n base for P3: l0..l2 -> n1..n3, l3->n12, l4->n8 ; t5->n9, t6->n10, t7->n11, t8->n13
    const int p3base = ((t & 7) << 1)
                     | (((t >> 3) & 1) << 12)
                     | (((t >> 4) & 1) << 8)
                     | (((t >> 5) & 1) << 9)
                     | (((t >> 6) & 1) << 10)
                     | (((t >> 7) & 1) << 11)
                     | ((t >> 8) << 13);

    // ===== FWHT #1, P1: bits {0,1,11,12,13}, coalesced global load =====
    {
        const float4* __restrict__ x4 = reinterpret_cast<const float4*>(x + row * L_N);
        const float4* __restrict__ B4 = reinterpret_cast<const float4*>(Bv);
#pragma unroll
        for (int k = 0; k < 8; k++) {
            float4 xv = x4[(k << 9) + t];
            float4 bv = B4[(k << 9) + t];
            r[4 * k + 0] = xv.x * bv.x;
            r[4 * k + 1] = xv.y * bv.y;
            r[4 * k + 2] = xv.z * bv.z;
            r[4 * k + 3] = xv.w * bv.w;
        }
    }
    fwht32(r);
#pragma unroll
    for (int k = 0; k < 8; k++) {
        int n = (k << 11) | (t << 2);
        *reinterpret_cast<float4*>(&s[sw(n)]) =
            make_float4(r[4 * k], r[4 * k + 1], r[4 * k + 2], r[4 * k + 3]);
    }
    __syncthreads();

    // ===== FWHT #1, P2: bits {2,3,8,9,10} =====
#pragma unroll
    for (int q = 0; q < 32; q++) {
        int n = p2base | ((q & 3) << 2) | ((q >> 2) << 8);
        r[q] = s[sw(n)];
    }
    fwht32(r);
#pragma unroll
    for (int q = 0; q < 32; q++) {
        int n = p2base | ((q & 3) << 2) | ((q >> 2) << 8);
        s[sw(n)] = r[q];
    }
    __syncthreads();

    // ===== FWHT #1, P3: bits {4,5,6,7} (bit 0 passenger) =====
#pragma unroll
    for (int ih = 0; ih < 16; ih++) {
        float2 v = *reinterpret_cast<const float2*>(&s[sw(p3base | (ih << 4))]);
        r[2 * ih] = v.x; r[2 * ih + 1] = v.y;
    }
    fwht16x2(r);
#pragma unroll
    for (int ih = 0; ih < 16; ih++) {
        *reinterpret_cast<float2*>(&s[sw(p3base | (ih << 4))]) =
            make_float2(r[2 * ih], r[2 * ih + 1]);
    }
    __syncthreads();

    // ===== permutation + G (into P3 layout) =====
#pragma unroll
    for (int ih = 0; ih < 16; ih++) {
        int n = p3base | (ih << 4);
        int2   p  = *reinterpret_cast<const int2*>(&Pi[n]);
        float2 gv = *reinterpret_cast<const float2*>(&Gv[n]);
        r[2 * ih]     = gv.x * s[sw(p.x)];
        r[2 * ih + 1] = gv.y * s[sw(p.y)];
    }
    __syncthreads();   // all gathers complete before smem is overwritten

    // ===== FWHT #2, P3: bits {4,5,6,7} =====
    fwht16x2(r);
#pragma unroll
    for (int ih = 0; ih < 16; ih++) {
        *reinterpret_cast<float2*>(&s[sw(p3base | (ih << 4))]) =
            make_float2(r[2 * ih], r[2 * ih + 1]);
    }
    __syncthreads();

    // ===== FWHT #2, P2: bits {2,3,8,9,10} =====
#pragma unroll
    for (int q = 0; q < 32; q++) {
        int n = p2base | ((q & 3) << 2) | ((q >> 2) << 8);
        r[q] = s[sw(n)];
    }
    fwht32(r);
#pragma unroll
    for (int q = 0; q < 32; q++) {
        int n = p2base | ((q & 3) << 2) | ((q >> 2) << 8);
        s[sw(n)] = r[q];
    }
    __syncthreads();

    // ===== FWHT #2, P1: bits {0,1,11,12,13}, scale, coalesced store =====
#pragma unroll
    for (int k = 0; k < 8; k++) {
        int n = (k << 11) | (t << 2);
        float4 v = *reinterpret_cast<const float4*>(&s[sw(n)]);
        r[4 * k + 0] = v.x; r[4 * k + 1] = v.y;
        r[4 * k + 2] = v.z; r[4 * k + 3] = v.w;
    }
    fwht32(r);
    {
        const float sc = 1.0f / 16384.0f;
        float4* __restrict__ o4 = reinterpret_cast<float4*>(out + row * L_N);
#pragma unroll
        for (int k = 0; k < 8; k++) {
            o4[(k << 9) + t] = make_float4(r[4 * k] * sc, r[4 * k + 1] * sc,
                                           r[4 * k + 2] * sc, r[4 * k + 3] * sc);
        }
    }
}

extern "C" void kernel_launch(void* const* d_in, const int* in_sizes, int n_in,
                              void* d_out, int out_size) {
    const float* x  = (const float*)d_in[0];
    const float* B  = (const float*)d_in[1];
    const float* G  = (const float*)d_in[2];
    const int*   Pi = (const int*)d_in[3];
    float* out = (float*)d_out;

    int rows = in_sizes[0] / L_N;

    cudaFuncSetAttribute(fwht_fused_kernel,
                         cudaFuncAttributeMaxDynamicSharedMemorySize, SMEM_BYTES);

    fwht_fused_kernel<<<rows, NT, SMEM_BYTES>>>(x, B, G, Pi, out);
}